// round 17
// baseline (speedup 1.0000x reference)
#include <cuda_runtime.h>
#include <cstdint>

#define HIDDEN 1024
#define HEADS  16
#define DKH    64
#define BB     2
#define NN     2048
#define ROWS   (BB*NN)

__device__ float g_Q[ROWS * HIDDEN];
__device__ float g_C[ROWS * HIDDEN];
__device__ float g_BM[(size_t)BB * NN * NN];      // bias + mask (33.5 MB)
// flash-ready K: [bh(32)][key(2048)][64 u32]  (tf32, permuted slot order)
__device__ uint32_t g_Kt[ROWS * HIDDEN];
// flash-ready V: [bh(32)][rp(1024)][128 u32]  (bf16 (h,l) interleaved pairs)
__device__ uint32_t g_V2[ROWS * HIDDEN];
// K-major bf16-split weights: [4 mats][512 kpairs][1024 n] u32 (h and l)
__device__ uint32_t g_Wh[4u * 512u * 1024u];
__device__ uint32_t g_Wl[4u * 512u * 1024u];

__device__ __forceinline__ uint32_t f2tf(float x) {
    uint32_t u; asm("cvt.rna.tf32.f32 %0, %1;" : "=r"(u) : "f"(x)); return u;
}
__device__ __forceinline__ uint32_t pk(float a, float b) {
    uint32_t r; asm("cvt.rn.bf16x2.f32 %0, %1, %2;" : "=r"(r) : "f"(b), "f"(a)); return r;
}
__device__ __forceinline__ float blo(uint32_t u) { return __uint_as_float(u << 16); }
__device__ __forceinline__ float bhi(uint32_t u) { return __uint_as_float(u & 0xffff0000u); }
__device__ __forceinline__ void sp(float f0, float f1, uint32_t& h, uint32_t& l) {
    h = pk(f0, f1);
    l = pk(f0 - blo(h), f1 - bhi(h));
}
__device__ __forceinline__ uint32_t smem_u32(const void* p) {
    uint32_t a;
    asm("{ .reg .u64 t; cvta.to.shared.u64 t, %1; cvt.u32.u64 %0, t; }" : "=r"(a) : "l"(p));
    return a;
}
__device__ __forceinline__ void cp16(uint32_t dst, const void* src) {
    asm volatile("cp.async.ca.shared.global [%0], [%1], 16;"
                 :: "r"(dst), "l"(src) : "memory");
}
__device__ __forceinline__ void mma8(float* d, uint32_t a0, uint32_t a1,
    uint32_t a2, uint32_t a3, uint32_t b0, uint32_t b1) {
    asm volatile("mma.sync.aligned.m16n8k8.row.col.f32.tf32.tf32.f32 "
        "{%0,%1,%2,%3},{%4,%5,%6,%7},{%8,%9},{%0,%1,%2,%3};"
        : "+f"(d[0]), "+f"(d[1]), "+f"(d[2]), "+f"(d[3])
        : "r"(a0), "r"(a1), "r"(a2), "r"(a3), "r"(b0), "r"(b1));
}
__device__ __forceinline__ void mma16(float* d, uint32_t a0, uint32_t a1,
    uint32_t a2, uint32_t a3, uint32_t b0, uint32_t b1) {
    asm volatile("mma.sync.aligned.m16n8k16.row.col.f32.bf16.bf16.f32 "
        "{%0,%1,%2,%3},{%4,%5,%6,%7},{%8,%9},{%0,%1,%2,%3};"
        : "+f"(d[0]), "+f"(d[1]), "+f"(d[2]), "+f"(d[3])
        : "r"(a0), "r"(a1), "r"(a2), "r"(a3), "r"(b0), "r"(b1));
}

// ---------------------------------------------------------------------------
__global__ void add_bm_kernel(const float* __restrict__ a,
                              const float* __restrict__ m,
                              float* __restrict__ o)
{
    int i = blockIdx.x * 256 + threadIdx.x;
    float4 x = ((const float4*)a)[i];
    float4 y = ((const float4*)m)[i];
    x.x += y.x; x.y += y.y; x.z += y.z; x.w += y.w;
    ((float4*)o)[i] = x;
}

__global__ void split_w_kernel(
    const float* __restrict__ W0, const float* __restrict__ W1,
    const float* __restrict__ W2, const float* __restrict__ W3,
    uint32_t* __restrict__ outH, uint32_t* __restrict__ outL)
{
    const float* W = (blockIdx.y == 0) ? W0 : (blockIdx.y == 1) ? W1
                   : (blockIdx.y == 2) ? W2 : W3;
    uint32_t* oh = outH + (size_t)blockIdx.y * 524288u;
    uint32_t* ol = outL + (size_t)blockIdx.y * 524288u;
    int idx = blockIdx.x * 256 + threadIdx.x;
    int kp = idx >> 10, n = idx & 1023;
    float w0 = W[(size_t)(2 * kp) * 1024 + n];
    float w1 = W[(size_t)(2 * kp + 1) * 1024 + n];
    uint32_t h, l;
    sp(w0, w1, h, l);
    oh[idx] = h; ol[idx] = l;
}

// ---------------------------------------------------------------------------
// bf16x3 GEMM — round-12 mainloop. Batched via z. Fused epilogues:
//   z==1 -> write K directly as tf32 in flash slot order (g_Kt layout)
//   z==2 -> write V directly as bf16 (h,l) row-pairs (g_V2 layout, shfl pair)
//   else -> plain fp32 C = acc + bias
// Conversions act on identical fp32 values as the old conv kernels.
// ---------------------------------------------------------------------------
__global__ void __launch_bounds__(256, 2) gemm_bf3_kernel(
    const float* __restrict__ A0, const float* __restrict__ A1,
    const float* __restrict__ A2,
    const uint32_t* __restrict__ WhG, const uint32_t* __restrict__ WlG,
    const float* __restrict__ b0, const float* __restrict__ b1,
    const float* __restrict__ b2,
    float* __restrict__ C0,
    uint32_t* __restrict__ KT, uint32_t* __restrict__ V2)
{
    __shared__ uint32_t Ah[2][8][136], Al[2][8][136], Wh[2][8][136], Wl[2][8][136];
    const int tid = threadIdx.x, lane = tid & 31, wid = tid >> 5;
    const int g = lane >> 2, t = lane & 3;
    const int wm = (wid & 3) * 32, wn = (wid >> 2) * 64;
    const int z = blockIdx.z;

    const float* A    = (z == 0) ? A0 : (z == 1) ? A1 : A2;
    const float* bias = (z == 0) ? b0 : (z == 1) ? b1 : b2;

    const float* Ab = A + (size_t)blockIdx.y * 128 * 1024;
    const uint32_t* WhB = WhG + (size_t)z * 524288u + blockIdx.x * 128;
    const uint32_t* WlB = WlG + (size_t)z * 524288u + blockIdx.x * 128;

    float acc[2][8][4];
#pragma unroll
    for (int mi = 0; mi < 2; mi++)
#pragma unroll
        for (int n = 0; n < 8; n++)
#pragma unroll
            for (int j = 0; j < 4; j++) acc[mi][n][j] = 0.f;

    const int arow = tid >> 2, ac4 = tid & 3;
    const int kp = tid >> 5, c4 = tid & 31;

    float4 ra0, ra1;
    uint4 rwh, rwl;
#define G_LOAD(k0) do { \
    ra0 = *(const float4*)(Ab + (size_t)arow * 1024 + (k0) + ac4 * 4); \
    ra1 = *(const float4*)(Ab + (size_t)(arow + 64) * 1024 + (k0) + ac4 * 4); \
    rwh = *(const uint4*)(WhB + (size_t)(((k0) >> 1) + kp) * 1024 + c4 * 4); \
    rwl = *(const uint4*)(WlB + (size_t)(((k0) >> 1) + kp) * 1024 + c4 * 4); \
} while (0)
#define G_STS(pb) do { \
    uint32_t h_, l_; \
    sp(ra0.x, ra0.y, h_, l_); Ah[pb][2*ac4][arow] = h_;      Al[pb][2*ac4][arow] = l_; \
    sp(ra0.z, ra0.w, h_, l_); Ah[pb][2*ac4+1][arow] = h_;    Al[pb][2*ac4+1][arow] = l_; \
    sp(ra1.x, ra1.y, h_, l_); Ah[pb][2*ac4][arow+64] = h_;   Al[pb][2*ac4][arow+64] = l_; \
    sp(ra1.z, ra1.w, h_, l_); Ah[pb][2*ac4+1][arow+64] = h_; Al[pb][2*ac4+1][arow+64] = l_; \
    *(uint4*)&Wh[pb][kp][c4 * 4] = rwh; \
    *(uint4*)&Wl[pb][kp][c4 * 4] = rwl; \
} while (0)

    G_LOAD(0);
    G_STS(0);
    __syncthreads();
    int p = 0;

    for (int k0 = 0; k0 < 1024; k0 += 16) {
        if (k0 + 16 < 1024) G_LOAD(k0 + 16);

        uint32_t af[2][8];
#pragma unroll
        for (int mi = 0; mi < 2; mi++) {
            int mb = wm + mi * 16;
            af[mi][0] = Ah[p][t][mb+g];   af[mi][1] = Ah[p][t][mb+g+8];
            af[mi][2] = Ah[p][t+4][mb+g]; af[mi][3] = Ah[p][t+4][mb+g+8];
            af[mi][4] = Al[p][t][mb+g];   af[mi][5] = Al[p][t][mb+g+8];
            af[mi][6] = Al[p][t+4][mb+g]; af[mi][7] = Al[p][t+4][mb+g+8];
        }
#pragma unroll
        for (int n = 0; n < 8; n++) {
            uint32_t b0h = Wh[p][t][wn+n*8+g], b1h = Wh[p][t+4][wn+n*8+g];
            uint32_t b0l = Wl[p][t][wn+n*8+g], b1l = Wl[p][t+4][wn+n*8+g];
#pragma unroll
            for (int mi = 0; mi < 2; mi++) {
                mma16(acc[mi][n], af[mi][0], af[mi][1], af[mi][2], af[mi][3], b0h, b1h);
                mma16(acc[mi][n], af[mi][4], af[mi][5], af[mi][6], af[mi][7], b0h, b1h);
                mma16(acc[mi][n], af[mi][0], af[mi][1], af[mi][2], af[mi][3], b0l, b1l);
            }
        }
        if (k0 + 16 < 1024) G_STS(p ^ 1);
        __syncthreads();
        p ^= 1;
    }

    // ---- epilogues ----
    const int bxb = blockIdx.x * 128;
    if (z == 1) {
        // K -> tf32, permuted slot order (identical to old conv_k output)
        const int slot0 = (t < 2) ? (4 * t)     : (4 * t - 7);   // dim j = 2t
        const int slot1 = (t < 2) ? (4 * t + 2) : (4 * t - 5);   // dim j = 2t+1
#pragma unroll
        for (int mi = 0; mi < 2; mi++) {
            int row0 = blockIdx.y * 128 + wm + mi * 16 + g;
#pragma unroll
            for (int n = 0; n < 8; n++) {
                int col = bxb + wn + n * 8 + 2 * t;
                float2 bv = *(const float2*)(bias + col);
                int hh = col >> 6, d = col & 63, kb = d >> 3;
#pragma unroll
                for (int r = 0; r < 2; r++) {
                    int row = row0 + r * 8;
                    int b = row >> 11, key = row & 2047;
                    uint32_t* dst = KT + ((size_t)(b * 16 + hh) * NN + key) * 64 + kb * 8;
                    dst[slot0] = f2tf(acc[mi][n][2 * r]     + bv.x);
                    dst[slot1] = f2tf(acc[mi][n][2 * r + 1] + bv.y);
                }
            }
        }
    } else if (z == 2) {
        // V -> bf16 (h,l) row-pairs (identical to old conv_v output)
#pragma unroll
        for (int mi = 0; mi < 2; mi++) {
            int row0 = blockIdx.y * 128 + wm + mi * 16 + g;
#pragma unroll
            for (int n = 0; n < 8; n++) {
                int col = bxb + wn + n * 8 + 2 * t;
                float2 bv = *(const float2*)(bias + col);
                float v0 = acc[mi][n][0] + bv.x;   // row row0,   col
                float v1 = acc[mi][n][1] + bv.y;   // row row0,   col+1
                float v2 = acc[mi][n][2] + bv.x;   // row row0+8, col
                float v3 = acc[mi][n][3] + bv.y;
                float o0 = __shfl_xor_sync(~0u, v0, 4);
                float o1 = __shfl_xor_sync(~0u, v1, 4);
                float o2 = __shfl_xor_sync(~0u, v2, 4);
                float o3 = __shfl_xor_sync(~0u, v3, 4);
                if ((g & 1) == 0) {
                    int hh = col >> 6, d = col & 63;
#pragma unroll
                    for (int r = 0; r < 2; r++) {
                        int row = row0 + r * 8;          // even
                        int b = row >> 11, key = row & 2047;
                        int rp = key >> 1;
                        uint32_t h0, l0, h1, l1;
                        if (r == 0) { sp(v0, o0, h0, l0); sp(v1, o1, h1, l1); }
                        else        { sp(v2, o2, h0, l0); sp(v3, o3, h1, l1); }
                        *(uint4*)(V2 + ((size_t)(b * 16 + hh) * (NN / 2) + rp) * 128 + d * 2)
                            = make_uint4(h0, l0, h1, l1);
                    }
                }
            }
        }
    } else {
        // plain fp32 C (Q projection and O projection)
#pragma unroll
        for (int mi = 0; mi < 2; mi++) {
            int row0 = blockIdx.y * 128 + wm + mi * 16 + g;
#pragma unroll
            for (int n = 0; n < 8; n++) {
                int col = bxb + wn + n * 8 + 2 * t;
                float2 bv = *(const float2*)(bias + col);
                *(float2*)(C0 + (size_t)row0 * 1024 + col) =
                    make_float2(acc[mi][n][0] + bv.x, acc[mi][n][1] + bv.y);
                *(float2*)(C0 + (size_t)(row0 + 8) * 1024 + col) =
                    make_float2(acc[mi][n][2] + bv.x, acc[mi][n][3] + bv.y);
            }
        }
    }
}

// ---------------------------------------------------------------------------
// Flash (round-16 verbatim): cp.async double-buffered pre-converted K/V.
// ---------------------------------------------------------------------------
#define FKSZ (64 * 72)
#define FVSZ (32 * 136)
#define FBUF (FKSZ + FVSZ)
#define FSM_BYTES (2 * FBUF * 4)

__global__ void __launch_bounds__(256, 2) flash_kernel(
    const uint32_t* __restrict__ Kt, const uint32_t* __restrict__ V2,
    const float* __restrict__ bm, float* __restrict__ ctx)
{
    extern __shared__ uint32_t smf[];

    const int tid = threadIdx.x, lane = tid & 31, wid = tid >> 5;
    const int g = lane >> 2, t = lane & 3;
    const int wrow = wid * 16;
    const int h = blockIdx.x, q0 = blockIdx.y * 128, b = blockIdx.z;
    const int bh = b * HEADS + h;

    const float* Qg = g_Q + ((size_t)b * NN + q0) * HIDDEN + h * DKH;
    const uint32_t* Ktg = Kt + (size_t)bh * NN * 64;
    const uint32_t* V2g = V2 + (size_t)bh * (NN / 2) * 128;

    const float L2E = 1.44269504088896340736f;
    const float QSC = 0.125f * L2E;

    uint32_t qa[8][4];
#pragma unroll
    for (int kb = 0; kb < 8; kb++) {
        qa[kb][0] = f2tf(__ldg(Qg + (size_t)(wrow+g)  *HIDDEN + kb*8 + t)   * QSC);
        qa[kb][1] = f2tf(__ldg(Qg + (size_t)(wrow+g+8)*HIDDEN + kb*8 + t)   * QSC);
        qa[kb][2] = f2tf(__ldg(Qg + (size_t)(wrow+g)  *HIDDEN + kb*8 + t+4) * QSC);
        qa[kb][3] = f2tf(__ldg(Qg + (size_t)(wrow+g+8)*HIDDEN + kb*8 + t+4) * QSC);
    }

    float Oa[8][4];
#pragma unroll
    for (int n = 0; n < 8; n++)
#pragma unroll
        for (int j = 0; j < 4; j++) Oa[n][j] = 0.f;
    float m0 = -1e30f, m1 = -1e30f, l0 = 0.f, l1 = 0.f;

    const float* bmB = bm + ((size_t)b * NN + q0 + wrow) * NN;

    const int kkey = tid >> 3, kkb = tid & 7;
    const int vrp  = tid >> 4, vdq = tid & 15;

    uint32_t kdst[2][2], vdst[2][2];
#pragma unroll
    for (int pb = 0; pb < 2; pb++) {
        uint32_t* Kp = smf + pb * FBUF;
        uint32_t* Vh = Kp + FKSZ;
#pragma unroll
        for (int i = 0; i < 2; i++) {
            kdst[pb][i] = smem_u32(&Kp[(kkey + i * 32) * 72 + kkb * 8]);
            vdst[pb][i] = smem_u32(&Vh[(vrp + i * 16) * 136 + vdq * 8]);
        }
    }
#define F_CP(pb, kt0) do { \
    const int k0_ = (kt0) * 64; \
    _Pragma("unroll") for (int i = 0; i < 2; i++) { \
        const uint32_t* kr = Ktg + (size_t)(k0_ + kkey + i * 32) * 64 + kkb * 8; \
        cp16(kdst[pb][i], kr); \
        cp16(kdst[pb][i] + 16, kr + 4); \
        const uint32_t* vr = V2g + (size_t)(k0_ / 2 + vrp + i * 16) * 128 + vdq * 8; \
        cp16(vdst[pb][i], vr); \
        cp16(vdst[pb][i] + 16, vr + 4); \
    } \
    asm volatile("cp.async.commit_group;" ::: "memory"); \
} while (0)

    F_CP(0, 0);
    asm volatile("cp.async.wait_group 0;" ::: "memory");
    __syncthreads();
    int p = 0;

    for (int kt = 0; kt < NN / 64; kt++) {
        const int k0 = kt * 64;
        if (kt + 1 < NN / 64) F_CP(p ^ 1, kt + 1);

        const uint32_t* Kp  = smf + p * FBUF;
        const uint32_t* Vhl = Kp + FKSZ;

        float sacc[8][4];
#pragma unroll
        for (int n = 0; n < 8; n++)
#pragma unroll
            for (int j = 0; j < 4; j++) sacc[n][j] = 0.f;
#pragma unroll
        for (int kb = 0; kb < 8; kb++)
#pragma unroll
            for (int n = 0; n < 8; n++) {
                uint2 bb = *(const uint2*)&Kp[(n*8+g) * 72 + kb*8 + 2*t];
                mma8(sacc[n], qa[kb][0], qa[kb][1], qa[kb][2], qa[kb][3], bb.x, bb.y);
            }

        float mx0 = -1e30f, mx1 = -1e30f;
#pragma unroll
        for (int n = 0; n < 8; n++) {
            float2 u = __ldg((const float2*)(bmB + (size_t)g    * NN + k0 + n*8 + 2*t));
            float2 w = __ldg((const float2*)(bmB + (size_t)(g+8)* NN + k0 + n*8 + 2*t));
            sacc[n][0] = fmaf(u.x, L2E, sacc[n][0]);
            sacc[n][1] = fmaf(u.y, L2E, sacc[n][1]);
            sacc[n][2] = fmaf(w.x, L2E, sacc[n][2]);
            sacc[n][3] = fmaf(w.y, L2E, sacc[n][3]);
            mx0 = fmaxf(mx0, fmaxf(sacc[n][0], sacc[n][1]));
            mx1 = fmaxf(mx1, fmaxf(sacc[n][2], sacc[n][3]));
        }
        mx0 = fmaxf(mx0, __shfl_xor_sync(~0u, mx0, 1));
        mx0 = fmaxf(mx0, __shfl_xor_sync(~0u, mx0, 2));
        mx1 = fmaxf(mx1, __shfl_xor_sync(~0u, mx1, 1));
        mx1 = fmaxf(mx1, __shfl_xor_sync(~0u, mx1, 2));
        float mn0 = fmaxf(m0, mx0), mn1 = fmaxf(m1, mx1);
        float c0 = exp2f(m0 - mn0), c1 = exp2f(m1 - mn1);
        float rs0 = 0.f, rs1 = 0.f;
#pragma unroll
        for (int n = 0; n < 8; n++) {
            sacc[n][0] = exp2f(sacc[n][0] - mn0);
            sacc[n][1] = exp2f(sacc[n][1] - mn0);
            sacc[n][2] = exp2f(sacc[n][2] - mn1);
            sacc[n][3] = exp2f(sacc[n][3] - mn1);
            rs0 += sacc[n][0] + sacc[n][1];
            rs1 += sacc[n][2] + sacc[n][3];
        }
        rs0 += __shfl_xor_sync(~0u, rs0, 1); rs0 += __shfl_xor_sync(~0u, rs0, 2);
        rs1 += __shfl_xor_sync(~0u, rs1, 1); rs1 += __shfl_xor_sync(~0u, rs1, 2);
        l0 = l0 * c0 + rs0; l1 = l1 * c1 + rs1;
        m0 = mn0; m1 = mn1;
#pragma unroll
        for (int n = 0; n < 8; n++) {
            Oa[n][0] *= c0; Oa[n][1] *= c0;
            Oa[n][2] *= c1; Oa[n][3] *= c1;
        }

#pragma unroll
        for (int kb = 0; kb < 4; kb++) {
            uint32_t a0h, a0l, a1h, a1l, a2h, a2l, a3h, a3l;
            sp(sacc[2*kb][0],   sacc[2*kb][1],   a0h, a0l);
            sp(sacc[2*kb][2],   sacc[2*kb][3],   a1h, a1l);
            sp(sacc[2*kb+1][0], sacc[2*kb+1][1], a2h, a2l);
            sp(sacc[2*kb+1][2], sacc[2*kb+1][3], a3h, a3l);
#pragma unroll
            for (int n = 0; n < 8; n++) {
                uint2 p0 = *(const uint2*)&Vhl[(kb*8+t)   * 136 + (n*8+g) * 2];
                uint2 p1 = *(const uint2*)&Vhl[(kb*8+t+4) * 136 + (n*8+g) * 2];
                mma16(Oa[n], a0h, a1h, a2h, a3h, p0.x, p1.x);
                mma16(Oa[n], a0l, a1l, a2l, a3l, p0.x, p1.x);
                mma16(Oa[n], a0h, a1h, a2h, a3h, p0.y, p1.y);
            }
        }

        if (kt + 1 < NN / 64)
            asm volatile("cp.async.wait_group 0;" ::: "memory");
        __syncthreads();
        p ^= 1;
    }

    float inv0 = 1.f / l0, inv1 = 1.f / l1;
    float* o0 = ctx + ((size_t)b * NN + q0 + wrow + g) * HIDDEN + h * DKH;
    float* o1 = o0 + (size_t)8 * HIDDEN;
#pragma unroll
    for (int n = 0; n < 8; n++) {
        *(float2*)&o0[n*8 + 2*t] = make_float2(Oa[n][0]*inv0, Oa[n][1]*inv0);
        *(float2*)&o1[n*8 + 2*t] = make_float2(Oa[n][2]*inv1, Oa[n][3]*inv1);
    }
}

extern "C" void kernel_launch(void* const* d_in, const int* in_sizes, int n_in,
                              void* d_out, int out_size)
{
    const float* q    = (const float*)d_in[0];
    const float* k    = (const float*)d_in[1];
    const float* v    = (const float*)d_in[2];
    const float* abia = (const float*)d_in[3];
    const float* amask= (const float*)d_in[4];
    const float* Wq   = (const float*)d_in[5];
    const float* bq   = (const float*)d_in[6];
    const float* Wk   = (const float*)d_in[7];
    const float* bk   = (const float*)d_in[8];
    const float* Wv   = (const float*)d_in[9];
    const float* bv   = (const float*)d_in[10];
    const float* Wo   = (const float*)d_in[11];
    const float* bo   = (const float*)d_in[12];
    float* out = (float*)d_out;

    float *Qp, *Cp, *BMp;
    uint32_t *WH, *WL, *KT, *V2;
    cudaGetSymbolAddress((void**)&Qp, g_Q);
    cudaGetSymbolAddress((void**)&Cp, g_C);
    cudaGetSymbolAddress((void**)&BMp, g_BM);
    cudaGetSymbolAddress((void**)&WH, g_Wh);
    cudaGetSymbolAddress((void**)&WL, g_Wl);
    cudaGetSymbolAddress((void**)&KT, g_Kt);
    cudaGetSymbolAddress((void**)&V2, g_V2);

    cudaFuncSetAttribute(flash_kernel,
                         cudaFuncAttributeMaxDynamicSharedMemorySize, FSM_BYTES);

    split_w_kernel<<<dim3(2048, 4), 256>>>(Wq, Wk, Wv, Wo, WH, WL);
    add_bm_kernel<<<8192, 256>>>(abia, amask, BMp);

    // batched Q/K/V projections; K and V epilogues write flash-ready formats
    dim3 gb3(HIDDEN / 128, ROWS / 128, 3);   // (8, 32, 3)
    gemm_bf3_kernel<<<gb3, 256>>>(q, k, v, WH, WL, bq, bk, bv, Qp, KT, V2);

    dim3 gf(HEADS, NN / 128, BB);            // (16, 16, 2)
    flash_kernel<<<gf, 256, FSM_BYTES>>>(KT, V2, BMp, Cp);

    // O projection (z = 0, W slice 3 via offset base)
    dim3 gb1(HIDDEN / 128, ROWS / 128, 1);
    gemm_bf3_kernel<<<gb1, 256>>>(Cp, Cp, Cp,
                                  WH + 1572864u, WL + 1572864u,
                                  bo, bo, bo, out, KT, V2);
}